// round 1
// baseline (speedup 1.0000x reference)
#include <cuda_runtime.h>
#include <cuda_bf16.h>
#include <math.h>

// Problem constants (static per reference)
#define KDIM 1024
#define BTOT 131072
#define NPOS 65536
#define NUNL 65536
#define KSEL 6553
#define NCOMB (NPOS + KSEL)

// -------------------- scratch (device globals; no allocation) --------------------
__device__ float               d_g2[KDIM];
__device__ int                 d_u_rows[NUNL];
__device__ int                 d_u_count;
__device__ unsigned long long  d_minpack[NUNL];   // (ordered float s)<<32 | argmin c
__device__ unsigned int        d_keys[NUNL];      // ordered-uint key for radix select
__device__ int                 d_plabel[NUNL];    // pseudo-label (argmin centroid)
__device__ int                 d_sel_label[BTOT]; // -1 = not selected (u rows only)
__device__ unsigned int        d_hist[256];
__device__ unsigned int        d_prefix;
__device__ int                 d_need;
__device__ unsigned int        d_T;
__device__ int                 d_selEq;
__device__ int                 d_eqctr;
__device__ double              d_acc;

// -------------------- helpers --------------------
__device__ __forceinline__ unsigned int ordf(float f) {
    unsigned int u = __float_as_uint(f);
    return (u & 0x80000000u) ? ~u : (u | 0x80000000u);
}
__device__ __forceinline__ float unordf(unsigned int u) {
    return __uint_as_float((u & 0x80000000u) ? (u ^ 0x80000000u) : ~u);
}

// 256-thread block sum (safe for sequential reuse)
__device__ __forceinline__ float blockSum256(float v) {
    __shared__ float sh[8];
    #pragma unroll
    for (int o = 16; o; o >>= 1) v += __shfl_down_sync(0xffffffffu, v, o);
    if ((threadIdx.x & 31) == 0) sh[threadIdx.x >> 5] = v;
    __syncthreads();
    float r = 0.f;
    if (threadIdx.x < 8) {
        r = sh[threadIdx.x];
        #pragma unroll
        for (int o = 4; o; o >>= 1) r += __shfl_down_sync(0xffu, r, o);
        if (threadIdx.x == 0) sh[0] = r;
    }
    __syncthreads();
    r = sh[0];
    __syncthreads();
    return r;
}

__device__ __forceinline__ float blockMax256(float v) {
    __shared__ float sh[8];
    #pragma unroll
    for (int o = 16; o; o >>= 1) v = fmaxf(v, __shfl_down_sync(0xffffffffu, v, o));
    if ((threadIdx.x & 31) == 0) sh[threadIdx.x >> 5] = v;
    __syncthreads();
    float r = -3.4e38f;
    if (threadIdx.x < 8) {
        r = sh[threadIdx.x];
        #pragma unroll
        for (int o = 4; o; o >>= 1) r = fmaxf(r, __shfl_down_sync(0xffu, r, o));
        if (threadIdx.x == 0) sh[0] = r;
    }
    __syncthreads();
    r = sh[0];
    __syncthreads();
    return r;
}

// -------------------- kernels --------------------
__global__ void init_kernel() {
    int i = blockIdx.x * blockDim.x + threadIdx.x;
    if (i < NUNL) d_minpack[i] = 0xFFFFFFFFFFFFFFFFULL;
    if (i < 256)  d_hist[i] = 0u;
    if (i == 0) {
        d_u_count = 0;
        d_prefix  = 0u;
        d_need    = KSEL;
        d_eqctr   = 0;
        d_acc     = 0.0;
    }
}

// ||g_c||^2 per centroid row
__global__ void g2_kernel(const float* __restrict__ gl) {
    int c = blockIdx.x;
    const float4* p = (const float4*)(gl + (size_t)c * KDIM);
    float4 v = p[threadIdx.x];
    float s = v.x * v.x + v.y * v.y + v.z * v.z + v.w * v.w;
    float tot = blockSum256(s);
    if (threadIdx.x == 0) d_g2[c] = tot;
}

// warp-aggregated compaction of unlabeled rows (order irrelevant for the mean)
__global__ void compact_kernel(const int* __restrict__ labels) {
    int i = blockIdx.x * blockDim.x + threadIdx.x;
    bool active = (labels[i] >= KDIM);
    unsigned mask = __ballot_sync(0xffffffffu, active);
    if (active) {
        int lane = threadIdx.x & 31;
        int rank = __popc(mask & ((1u << lane) - 1u));
        int base = 0;
        int leader = __ffs(mask) - 1;
        if (lane == leader) base = atomicAdd(&d_u_count, __popc(mask));
        base = __shfl_sync(mask, base, leader);
        d_u_rows[base + rank] = i;
    }
}

// 128x128x16 SGEMM tile, fused per-row min/argmin of (g2[c] - 2*dot) epilogue
#define BM 128
#define BN 128
#define BKK 16

__global__ void __launch_bounds__(256)
gemm_min_kernel(const float* __restrict__ A, const float* __restrict__ Bm) {
    __shared__ float As[BKK][BM];
    __shared__ float Bs[BKK][BN];
    __shared__ unsigned long long smin[BM];
    __shared__ int rowsS[BM];

    int tid = threadIdx.x;
    int bn = blockIdx.x, bm = blockIdx.y;
    int tx = tid & 15, ty = tid >> 4;

    if (tid < BM) {
        rowsS[tid] = d_u_rows[bm * BM + tid];
        smin[tid]  = 0xFFFFFFFFFFFFFFFFULL;
    }
    __syncthreads();

    float acc[8][8];
    #pragma unroll
    for (int i = 0; i < 8; i++)
        #pragma unroll
        for (int j = 0; j < 8; j++) acc[i][j] = 0.f;

    // each thread loads two float4s of A and two of B per k-tile
    int id0 = tid * 2;
    int ar0 = id0 >> 2,       ak0 = (id0 & 3) * 4;
    int ar1 = (id0 + 1) >> 2, ak1 = ((id0 + 1) & 3) * 4;

    for (int kt = 0; kt < KDIM; kt += BKK) {
        float4 a0 = __ldg((const float4*)(A  + (size_t)rowsS[ar0] * KDIM + kt + ak0));
        float4 a1 = __ldg((const float4*)(A  + (size_t)rowsS[ar1] * KDIM + kt + ak1));
        float4 b0 = __ldg((const float4*)(Bm + (size_t)(bn * BN + ar0) * KDIM + kt + ak0));
        float4 b1 = __ldg((const float4*)(Bm + (size_t)(bn * BN + ar1) * KDIM + kt + ak1));

        As[ak0 + 0][ar0] = a0.x; As[ak0 + 1][ar0] = a0.y;
        As[ak0 + 2][ar0] = a0.z; As[ak0 + 3][ar0] = a0.w;
        As[ak1 + 0][ar1] = a1.x; As[ak1 + 1][ar1] = a1.y;
        As[ak1 + 2][ar1] = a1.z; As[ak1 + 3][ar1] = a1.w;
        Bs[ak0 + 0][ar0] = b0.x; Bs[ak0 + 1][ar0] = b0.y;
        Bs[ak0 + 2][ar0] = b0.z; Bs[ak0 + 3][ar0] = b0.w;
        Bs[ak1 + 0][ar1] = b1.x; Bs[ak1 + 1][ar1] = b1.y;
        Bs[ak1 + 2][ar1] = b1.z; Bs[ak1 + 3][ar1] = b1.w;
        __syncthreads();

        #pragma unroll
        for (int k = 0; k < BKK; k++) {
            float4 av0 = *(const float4*)&As[k][ty * 8];
            float4 av1 = *(const float4*)&As[k][ty * 8 + 4];
            float4 bv0 = *(const float4*)&Bs[k][tx * 8];
            float4 bv1 = *(const float4*)&Bs[k][tx * 8 + 4];
            float a[8] = {av0.x, av0.y, av0.z, av0.w, av1.x, av1.y, av1.z, av1.w};
            float b[8] = {bv0.x, bv0.y, bv0.z, bv0.w, bv1.x, bv1.y, bv1.z, bv1.w};
            #pragma unroll
            for (int i = 0; i < 8; i++)
                #pragma unroll
                for (int j = 0; j < 8; j++)
                    acc[i][j] += a[i] * b[j];
        }
        __syncthreads();
    }

    // epilogue: per-row min/argmin of s = g2[c] - 2*dot, packed into u64
    float g2v[8];
    #pragma unroll
    for (int j = 0; j < 8; j++) g2v[j] = d_g2[bn * BN + tx * 8 + j];

    #pragma unroll
    for (int i = 0; i < 8; i++) {
        unsigned long long best = 0xFFFFFFFFFFFFFFFFULL;
        #pragma unroll
        for (int j = 0; j < 8; j++) {
            float v = g2v[j] - 2.0f * acc[i][j];
            unsigned long long p =
                ((unsigned long long)ordf(v) << 32) | (unsigned)(bn * BN + tx * 8 + j);
            best = (p < best) ? p : best;
        }
        atomicMin(&smin[ty * 8 + i], best);
    }
    __syncthreads();
    if (tid < BM) atomicMin(&d_minpack[bm * BM + tid], smin[tid]);
}

// per-u: key = max(||u||^2 + s_min, 0), ordered; pseudo-label = argmin
__global__ void keys_kernel(const float* __restrict__ outputs) {
    int u = blockIdx.x;
    int row = d_u_rows[u];
    const float4* p = (const float4*)(outputs + (size_t)row * KDIM);
    float4 v = p[threadIdx.x];
    float s = v.x * v.x + v.y * v.y + v.z * v.z + v.w * v.w;
    float u2 = blockSum256(s);
    if (threadIdx.x == 0) {
        unsigned long long pk = d_minpack[u];
        float smin = unordf((unsigned int)(pk >> 32));
        float key = u2 + smin;
        if (key < 0.f) key = 0.f;
        d_keys[u]   = ordf(key);
        d_plabel[u] = (int)(pk & 0xFFFFFFFFu);
    }
}

// 4-pass radix select: find value of KSEL-th smallest key
__global__ void hist_kernel(int shift) {
    __shared__ unsigned int sh[256];
    sh[threadIdx.x] = 0u;
    __syncthreads();
    unsigned int prefix = d_prefix;
    unsigned int known  = (shift == 24) ? 0u : (0xFFFFFFFFu << (shift + 8));
    for (int i = blockIdx.x * blockDim.x + threadIdx.x; i < NUNL;
         i += gridDim.x * blockDim.x) {
        unsigned int k = d_keys[i];
        if ((k & known) == (prefix & known))
            atomicAdd(&sh[(k >> shift) & 0xFFu], 1u);
    }
    __syncthreads();
    if (sh[threadIdx.x]) atomicAdd(&d_hist[threadIdx.x], sh[threadIdx.x]);
}

__global__ void scan_kernel(int shift) {
    __shared__ unsigned int sh[256];
    sh[threadIdx.x] = d_hist[threadIdx.x];
    __syncthreads();
    if (threadIdx.x == 0) {
        int need = d_need;
        unsigned int cum = 0;
        int b = 255;
        for (int i = 0; i < 256; i++) {
            unsigned int c2 = cum + sh[i];
            if ((int)c2 >= need) { b = i; break; }
            cum = c2;
        }
        d_prefix |= ((unsigned int)b << shift);
        d_need = need - (int)cum;
        if (shift == 0) {
            d_T = d_prefix;     // exact key value of KSEL-th smallest
            d_selEq = d_need;   // how many of the equal keys to take
            d_eqctr = 0;
        }
    }
    __syncthreads();
    d_hist[threadIdx.x] = 0u;   // ready for next pass
}

__global__ void select_kernel() {
    int u = blockIdx.x * blockDim.x + threadIdx.x;
    if (u >= NUNL) return;
    unsigned int k = d_keys[u];
    unsigned int T = d_T;
    int lbl = -1;
    if (k < T) lbl = d_plabel[u];
    else if (k == T) {
        if (atomicAdd(&d_eqctr, 1) < d_selEq) lbl = d_plabel[u];
    }
    d_sel_label[d_u_rows[u]] = lbl;
}

// cross entropy over P rows + selected U rows, double accumulator
__global__ void ce_kernel(const float* __restrict__ outputs,
                          const int* __restrict__ labels) {
    int r = blockIdx.x;
    int lab = labels[r];
    int target = (lab < KDIM) ? lab : d_sel_label[r];
    if (target < 0) return;
    const float4* p = (const float4*)(outputs + (size_t)r * KDIM);
    float4 v = p[threadIdx.x];
    float m = fmaxf(fmaxf(v.x, v.y), fmaxf(v.z, v.w));
    float M = blockMax256(m);
    float e = expf(v.x - M) + expf(v.y - M) + expf(v.z - M) + expf(v.w - M);
    float S = blockSum256(e);
    if (threadIdx.x == 0) {
        float xt = outputs[(size_t)r * KDIM + target];
        float nll = logf(S) + M - xt;
        atomicAdd(&d_acc, (double)nll);
    }
}

__global__ void finish_kernel(float* out) {
    out[0] = (float)(d_acc / (double)NCOMB);
}

// -------------------- launch --------------------
extern "C" void kernel_launch(void* const* d_in, const int* in_sizes, int n_in,
                              void* d_out, int out_size) {
    const float* outputs = (const float*)d_in[0];
    const int*   labels  = (const int*)d_in[1];
    const float* gl      = (const float*)d_in[2];
    float* out = (float*)d_out;

    init_kernel<<<256, 256>>>();
    g2_kernel<<<KDIM, 256>>>(gl);
    compact_kernel<<<BTOT / 256, 256>>>(labels);
    gemm_min_kernel<<<dim3(KDIM / BN, NUNL / BM), 256>>>(outputs, gl);
    keys_kernel<<<NUNL, 256>>>(outputs);
    for (int pass = 0; pass < 4; pass++) {
        int shift = 24 - 8 * pass;
        hist_kernel<<<64, 256>>>(shift);
        scan_kernel<<<1, 256>>>(shift);
    }
    select_kernel<<<NUNL / 256, 256>>>();
    ce_kernel<<<BTOT, 256>>>(outputs, labels);
    finish_kernel<<<1, 1>>>(out);
}

// round 10
// speedup vs baseline: 5.3059x; 5.3059x over previous
#include <cuda_runtime.h>
#include <cuda_bf16.h>
#include <cstdint>
#include <math.h>

// Problem constants (static per reference)
#define KDIM 1024
#define BTOT 131072
#define NPOS 65536
#define NUNL 65536
#define KSEL 6553
#define NCOMB (NPOS + KSEL)

// GEMM tiling: CTA 128x128, 8 warps (2m x 4n), warp 64x32, K-stage 64
#define BM 128
#define BN 128
#define BK 64
#define N_CHUNKS (KDIM / BN)      // 8
#define K_STAGES (KDIM / BK)      // 16
#define TOT_IT   (N_CHUNKS * K_STAGES)  // 128
#define GRID_M   (NUNL / BM)      // 512

// dynamic SMEM layout (bytes)
#define SM_A    0                  // 2 stages x 16KB
#define SM_B    32768              // 2 stages x 16KB
#define SM_G2   65536              // 1024 floats
#define SM_MIN  69632              // 128 x u64
#define SMEM_TOTAL 70656

// -------------------- scratch (device globals; no allocation) --------------------
__device__ __align__(256) __nv_bfloat16 d_Abf[(size_t)NUNL * KDIM];   // 128MB
__device__ __align__(256) __nv_bfloat16 d_Bbf[(size_t)KDIM * KDIM];   // 2MB
__device__ float               d_g2[KDIM];
__device__ float               d_u2[NUNL];
__device__ unsigned long long  d_minpack[NUNL];   // (ordered float s)<<32 | argmin c
__device__ unsigned int        d_keys[NUNL];
__device__ int                 d_plabel[NUNL];
__device__ int                 d_sel_label[BTOT];
__device__ unsigned int        d_hist[256];
__device__ unsigned int        d_prefix;
__device__ int                 d_need;
__device__ unsigned int        d_T;
__device__ int                 d_selEq;
__device__ int                 d_eqctr;
__device__ double              d_acc;

// -------------------- PTX helpers (all legal at compute_103 virtual arch) -----
__device__ __forceinline__ uint32_t smem_to_u32(const void* p) {
    uint32_t a;
    asm("{ .reg .u64 t; cvta.to.shared.u64 t, %1; cvt.u32.u64 %0, t; }" : "=r"(a) : "l"(p));
    return a;
}
__device__ __forceinline__ void cp16(uint32_t saddr, const void* gaddr) {
    asm volatile("cp.async.cg.shared.global [%0], [%1], 16;" :: "r"(saddr), "l"(gaddr));
}
#define CP_COMMIT() asm volatile("cp.async.commit_group;" ::: "memory")
#define CP_WAIT1()  asm volatile("cp.async.wait_group 1;" ::: "memory")
#define CP_WAIT0()  asm volatile("cp.async.wait_group 0;" ::: "memory")

__device__ __forceinline__ void ldsm_x4(uint32_t& r0, uint32_t& r1, uint32_t& r2,
                                        uint32_t& r3, uint32_t addr) {
    asm volatile("ldmatrix.sync.aligned.m8n8.x4.shared.b16 {%0,%1,%2,%3}, [%4];"
                 : "=r"(r0), "=r"(r1), "=r"(r2), "=r"(r3) : "r"(addr));
}
__device__ __forceinline__ void mma_bf16(float* c, uint32_t a0, uint32_t a1,
                                         uint32_t a2, uint32_t a3,
                                         uint32_t b0, uint32_t b1) {
    asm volatile("mma.sync.aligned.m16n8k16.row.col.f32.bf16.bf16.f32 "
                 "{%0,%1,%2,%3},{%4,%5,%6,%7},{%8,%9},{%0,%1,%2,%3};"
                 : "+f"(c[0]), "+f"(c[1]), "+f"(c[2]), "+f"(c[3])
                 : "r"(a0), "r"(a1), "r"(a2), "r"(a3), "r"(b0), "r"(b1));
}

// SW128 swizzle on byte offsets (128B rows): conflict-free ldmatrix
#define SWZ(x) ((x) ^ (((x) >> 3) & 0x70))

// -------------------- small helpers --------------------
__device__ __forceinline__ unsigned int ordf(float f) {
    unsigned int u = __float_as_uint(f);
    return (u & 0x80000000u) ? ~u : (u | 0x80000000u);
}
__device__ __forceinline__ float unordf(unsigned int u) {
    return __uint_as_float((u & 0x80000000u) ? (u ^ 0x80000000u) : ~u);
}

__device__ __forceinline__ float blockSum256(float v) {
    __shared__ float sh[8];
    #pragma unroll
    for (int o = 16; o; o >>= 1) v += __shfl_down_sync(0xffffffffu, v, o);
    if ((threadIdx.x & 31) == 0) sh[threadIdx.x >> 5] = v;
    __syncthreads();
    float r = 0.f;
    if (threadIdx.x < 8) {
        r = sh[threadIdx.x];
        #pragma unroll
        for (int o = 4; o; o >>= 1) r += __shfl_down_sync(0xffu, r, o);
        if (threadIdx.x == 0) sh[0] = r;
    }
    __syncthreads();
    r = sh[0];
    __syncthreads();
    return r;
}
__device__ __forceinline__ float blockMax256(float v) {
    __shared__ float sh[8];
    #pragma unroll
    for (int o = 16; o; o >>= 1) v = fmaxf(v, __shfl_down_sync(0xffffffffu, v, o));
    if ((threadIdx.x & 31) == 0) sh[threadIdx.x >> 5] = v;
    __syncthreads();
    float r = -3.4e38f;
    if (threadIdx.x < 8) {
        r = sh[threadIdx.x];
        #pragma unroll
        for (int o = 4; o; o >>= 1) r = fmaxf(r, __shfl_down_sync(0xffu, r, o));
        if (threadIdx.x == 0) sh[0] = r;
    }
    __syncthreads();
    r = sh[0];
    __syncthreads();
    return r;
}

// -------------------- kernels --------------------
__global__ void init_kernel() {
    if (threadIdx.x < 256) d_hist[threadIdx.x] = 0u;
    if (threadIdx.x == 0) {
        d_prefix = 0u;
        d_need   = KSEL;
        d_eqctr  = 0;
        d_acc    = 0.0;
    }
}

// fp32 -> bf16 conversion for U rows and global_logit, fused with row-norm sums
__global__ void convert_kernel(const float* __restrict__ outputs,
                               const float* __restrict__ gl) {
    int row = blockIdx.x;              // [0, NUNL+KDIM)
    bool isA = (row < NUNL);
    const float* src = isA ? outputs + (size_t)(NPOS + row) * KDIM
                           : gl + (size_t)(row - NUNL) * KDIM;
    __nv_bfloat16* dst = isA ? d_Abf + (size_t)row * KDIM
                             : d_Bbf + (size_t)(row - NUNL) * KDIM;
    int t = threadIdx.x;               // 128 threads, 8 floats each
    float4 v0 = ((const float4*)src)[2 * t];
    float4 v1 = ((const float4*)src)[2 * t + 1];
    float s = v0.x * v0.x + v0.y * v0.y + v0.z * v0.z + v0.w * v0.w
            + v1.x * v1.x + v1.y * v1.y + v1.z * v1.z + v1.w * v1.w;
    __nv_bfloat162 h0 = __floats2bfloat162_rn(v0.x, v0.y);
    __nv_bfloat162 h1 = __floats2bfloat162_rn(v0.z, v0.w);
    __nv_bfloat162 h2 = __floats2bfloat162_rn(v1.x, v1.y);
    __nv_bfloat162 h3 = __floats2bfloat162_rn(v1.z, v1.w);
    uint4 pk;
    pk.x = *reinterpret_cast<unsigned int*>(&h0);
    pk.y = *reinterpret_cast<unsigned int*>(&h1);
    pk.z = *reinterpret_cast<unsigned int*>(&h2);
    pk.w = *reinterpret_cast<unsigned int*>(&h3);
    ((uint4*)dst)[t] = pk;

    __shared__ float sh[4];
    #pragma unroll
    for (int o = 16; o; o >>= 1) s += __shfl_down_sync(0xffffffffu, s, o);
    if ((t & 31) == 0) sh[t >> 5] = s;
    __syncthreads();
    if (t == 0) {
        float tot = sh[0] + sh[1] + sh[2] + sh[3];
        if (isA) d_u2[row] = tot;
        else     d_g2[row - NUNL] = tot;
    }
}

// bf16 HMMA GEMM (dot[u,c]) with fused min/argmin of (g2[c] - 2*dot) epilogue.
// 512 CTAs x 256 threads; warp grid 2(m) x 4(n); warp tile 64x32.
__global__ void __launch_bounds__(256, 2) gemm_kernel() {
    extern __shared__ char smem[];
    uint32_t sb = smem_to_u32(smem);
    int tid = threadIdx.x;
    int wid = tid >> 5;
    int lane = tid & 31;
    int warp_m = wid >> 2;         // 0..1
    int warp_n = wid & 3;          // 0..3

    float* g2s = (float*)(smem + SM_G2);
    unsigned long long* smin = (unsigned long long*)(smem + SM_MIN);

    // init epilogue smem
    ((float4*)g2s)[tid] = ((const float4*)d_g2)[tid];     // 256 * 16B = 4KB
    if (tid < BM) smin[tid] = 0xFFFFFFFFFFFFFFFFULL;

    const char* Abase = (const char*)d_Abf + (size_t)blockIdx.x * BM * (KDIM * 2);
    const char* Bbase = (const char*)d_Bbf;

    auto load_stage = [&](int it) {
        int nb = it >> 4, kt = it & 15;
        uint32_t abuf = sb + SM_A + (it & 1) * 16384;
        uint32_t bbuf = sb + SM_B + (it & 1) * 16384;
        const char* Ag = Abase + (size_t)kt * 128;
        const char* Bg = Bbase + (size_t)nb * BN * (KDIM * 2) + (size_t)kt * 128;
        #pragma unroll
        for (int q = 0; q < 4; q++) {
            int idx = q * 256 + tid;
            int r = idx >> 3, u = idx & 7;
            cp16(abuf + SWZ(r * 128 + u * 16), Ag + (size_t)r * 2048 + u * 16);
            cp16(bbuf + SWZ(r * 128 + u * 16), Bg + (size_t)r * 2048 + u * 16);
        }
        CP_COMMIT();
    };

    float acc[4][4][4];
    #pragma unroll
    for (int mt = 0; mt < 4; mt++)
        #pragma unroll
        for (int nt = 0; nt < 4; nt++)
            #pragma unroll
            for (int j = 0; j < 4; j++) acc[mt][nt][j] = 0.f;

    load_stage(0);
    for (int it = 0; it < TOT_IT; it++) {
        if (it + 1 < TOT_IT) { load_stage(it + 1); CP_WAIT1(); }
        else                 { CP_WAIT0(); }
        __syncthreads();

        // compute on buffer it&1: 4 k16-steps
        uint32_t aoff = sb + SM_A + (it & 1) * 16384;
        uint32_t boff = sb + SM_B + (it & 1) * 16384;
        #pragma unroll
        for (int ks = 0; ks < 4; ks++) {
            uint32_t a[4][4];
            #pragma unroll
            for (int mt = 0; mt < 4; mt++) {
                int row = warp_m * 64 + mt * 16 + (lane & 15);
                uint32_t addr = aoff + SWZ(row * 128 + ks * 32 + ((lane >> 4) * 16));
                ldsm_x4(a[mt][0], a[mt][1], a[mt][2], a[mt][3], addr);
            }
            uint32_t b[4][2];
            #pragma unroll
            for (int h = 0; h < 2; h++) {
                int row = warp_n * 32 + h * 16 + ((lane >> 4) << 3) + (lane & 7);
                uint32_t addr = boff + SWZ(row * 128 + ks * 32 + (((lane >> 3) & 1) * 16));
                uint32_t r0, r1, r2, r3;
                ldsm_x4(r0, r1, r2, r3, addr);
                b[2 * h][0] = r0; b[2 * h][1] = r1;
                b[2 * h + 1][0] = r2; b[2 * h + 1][1] = r3;
            }
            #pragma unroll
            for (int mt = 0; mt < 4; mt++)
                #pragma unroll
                for (int nt = 0; nt < 4; nt++)
                    mma_bf16(acc[mt][nt], a[mt][0], a[mt][1], a[mt][2], a[mt][3],
                             b[nt][0], b[nt][1]);
        }

        // end of an n-chunk: fold accumulators into the running min, reset
        if ((it & 15) == 15) {
            int nb = it >> 4;
            #pragma unroll
            for (int mt = 0; mt < 4; mt++) {
                unsigned long long bestA = 0xFFFFFFFFFFFFFFFFULL;
                unsigned long long bestB = 0xFFFFFFFFFFFFFFFFULL;
                #pragma unroll
                for (int nt = 0; nt < 4; nt++) {
                    int col = nb * BN + warp_n * 32 + nt * 8 + (lane & 3) * 2;
                    #pragma unroll
                    for (int j = 0; j < 2; j++) {
                        float s0 = g2s[col + j] - 2.0f * acc[mt][nt][j];
                        unsigned long long p =
                            ((unsigned long long)ordf(s0) << 32) | (unsigned)(col + j);
                        bestA = (p < bestA) ? p : bestA;
                        float s1 = g2s[col + j] - 2.0f * acc[mt][nt][2 + j];
                        p = ((unsigned long long)ordf(s1) << 32) | (unsigned)(col + j);
                        bestB = (p < bestB) ? p : bestB;
                        acc[mt][nt][j] = 0.f;
                        acc[mt][nt][2 + j] = 0.f;
                    }
                }
                int row0 = warp_m * 64 + mt * 16 + (lane >> 2);
                atomicMin(&smin[row0], bestA);
                atomicMin(&smin[row0 + 8], bestB);
            }
        }
        __syncthreads();
    }

    if (tid < BM) d_minpack[blockIdx.x * BM + tid] = smin[tid];
}

// key = max(u2 + s_min, 0); pseudo-label = argmin
__global__ void keys2_kernel() {
    int u = blockIdx.x * 256 + threadIdx.x;
    unsigned long long pk = d_minpack[u];
    float smin = unordf((unsigned int)(pk >> 32));
    float key = d_u2[u] + smin;
    if (key < 0.f) key = 0.f;
    d_keys[u]   = ordf(key);
    d_plabel[u] = (int)(pk & 0xFFFFFFFFu);
}

// 4-pass radix select for the KSEL-th smallest key
__global__ void hist_kernel(int shift) {
    __shared__ unsigned int sh[256];
    sh[threadIdx.x] = 0u;
    __syncthreads();
    unsigned int prefix = d_prefix;
    unsigned int known  = (shift == 24) ? 0u : (0xFFFFFFFFu << (shift + 8));
    for (int i = blockIdx.x * blockDim.x + threadIdx.x; i < NUNL;
         i += gridDim.x * blockDim.x) {
        unsigned int k = d_keys[i];
        if ((k & known) == (prefix & known))
            atomicAdd(&sh[(k >> shift) & 0xFFu], 1u);
    }
    __syncthreads();
    if (sh[threadIdx.x]) atomicAdd(&d_hist[threadIdx.x], sh[threadIdx.x]);
}

__global__ void scan_kernel(int shift) {
    __shared__ unsigned int sh[256];
    sh[threadIdx.x] = d_hist[threadIdx.x];
    __syncthreads();
    if (threadIdx.x == 0) {
        int need = d_need;
        unsigned int cum = 0;
        int b = 255;
        for (int i = 0; i < 256; i++) {
            unsigned int c2 = cum + sh[i];
            if ((int)c2 >= need) { b = i; break; }
            cum = c2;
        }
        d_prefix |= ((unsigned int)b << shift);
        d_need = need - (int)cum;
        if (shift == 0) {
            d_T = d_prefix;
            d_selEq = d_need;
            d_eqctr = 0;
        }
    }
    __syncthreads();
    d_hist[threadIdx.x] = 0u;
}

__global__ void select_kernel() {
    int u = blockIdx.x * blockDim.x + threadIdx.x;
    if (u >= NUNL) return;
    unsigned int k = d_keys[u];
    unsigned int T = d_T;
    int lbl = -1;
    if (k < T) lbl = d_plabel[u];
    else if (k == T) {
        if (atomicAdd(&d_eqctr, 1) < d_selEq) lbl = d_plabel[u];
    }
    d_sel_label[NPOS + u] = lbl;
}

// cross entropy over P rows + selected U rows, double accumulator
__global__ void ce_kernel(const float* __restrict__ outputs,
                          const int* __restrict__ labels) {
    int r = blockIdx.x;
    int lab = labels[r];
    int target = (lab < KDIM) ? lab : d_sel_label[r];
    if (target < 0) return;
    const float4* p = (const float4*)(outputs + (size_t)r * KDIM);
    float4 v = p[threadIdx.x];
    float m = fmaxf(fmaxf(v.x, v.y), fmaxf(v.z, v.w));
    float M = blockMax256(m);
    float e = expf(v.x - M) + expf(v.y - M) + expf(v.z - M) + expf(v.w - M);
    float S = blockSum256(e);
    if (threadIdx.x == 0) {
        float xt = outputs[(size_t)r * KDIM + target];
        float nll = logf(S) + M - xt;
        atomicAdd(&d_acc, (double)nll);
    }
}

__global__ void finish_kernel(float* out) {
    out[0] = (float)(d_acc / (double)NCOMB);
}

// -------------------- launch --------------------
extern "C" void kernel_launch(void* const* d_in, const int* in_sizes, int n_in,
                              void* d_out, int out_size) {
    const float* outputs = (const float*)d_in[0];
    const int*   labels  = (const int*)d_in[1];
    const float* gl      = (const float*)d_in[2];
    float* out = (float*)d_out;

    cudaFuncSetAttribute(gemm_kernel, cudaFuncAttributeMaxDynamicSharedMemorySize,
                         SMEM_TOTAL);

    init_kernel<<<1, 256>>>();
    convert_kernel<<<NUNL + KDIM, 128>>>(outputs, gl);
    gemm_kernel<<<GRID_M, 256, SMEM_TOTAL>>>();
    keys2_kernel<<<NUNL / 256, 256>>>();
    for (int pass = 0; pass < 4; pass++) {
        int shift = 24 - 8 * pass;
        hist_kernel<<<64, 256>>>(shift);
        scan_kernel<<<1, 256>>>(shift);
    }
    select_kernel<<<NUNL / 256, 256>>>();
    ce_kernel<<<BTOT, 256>>>(outputs, labels);
    finish_kernel<<<1, 1>>>(out);
}

// round 12
// speedup vs baseline: 5.4116x; 1.0199x over previous
#include <cuda_runtime.h>
#include <cuda_bf16.h>
#include <cstdint>
#include <math.h>

// Problem constants (static per reference)
#define KDIM 1024
#define BTOT 131072
#define NPOS 65536
#define NUNL 65536
#define KSEL 6553
#define NCOMB (NPOS + KSEL)

// GEMM tiling: CTA 128x128, 8 warps (2m x 4n), warp 64x32, K-stage 64
#define BM 128
#define BN 128
#define BK 64
#define N_CHUNKS (KDIM / BN)      // 8
#define K_STAGES (KDIM / BK)      // 16
#define TOT_IT   (N_CHUNKS * K_STAGES)  // 128
#define GRID_M   (NUNL / BM)      // 512

// dynamic SMEM layout (bytes): 3-stage pipeline
#define SM_A    0                  // 3 stages x 16KB
#define SM_B    49152              // 3 stages x 16KB
#define SM_G2   98304              // 1024 floats
#define SM_MIN  102400             // 128 x u64
#define SMEM_TOTAL 103424

// -------------------- scratch (device globals; no allocation) --------------------
__device__ __align__(256) __nv_bfloat16 d_Abf[(size_t)NUNL * KDIM];   // 128MB
__device__ __align__(256) __nv_bfloat16 d_Bbf[(size_t)KDIM * KDIM];   // 2MB
__device__ float               d_g2[KDIM];
__device__ float               d_u2[NUNL];
__device__ unsigned long long  d_minpack[NUNL];   // (ordered float s)<<32 | argmin c
__device__ unsigned int        d_keys[NUNL];
__device__ int                 d_plabel[NUNL];
__device__ int                 d_sel_label[BTOT];
__device__ unsigned int        d_hist[256];
__device__ unsigned int        d_prefix;
__device__ int                 d_need;
__device__ unsigned int        d_T;
__device__ int                 d_selEq;
__device__ int                 d_eqctr;
__device__ double              d_acc;

// -------------------- PTX helpers (all legal at compute_103 virtual arch) -----
__device__ __forceinline__ uint32_t smem_to_u32(const void* p) {
    uint32_t a;
    asm("{ .reg .u64 t; cvta.to.shared.u64 t, %1; cvt.u32.u64 %0, t; }" : "=r"(a) : "l"(p));
    return a;
}
__device__ __forceinline__ void cp16(uint32_t saddr, const void* gaddr) {
    asm volatile("cp.async.cg.shared.global [%0], [%1], 16;" :: "r"(saddr), "l"(gaddr));
}
#define CP_COMMIT() asm volatile("cp.async.commit_group;" ::: "memory")
#define CP_WAIT1()  asm volatile("cp.async.wait_group 1;" ::: "memory")
#define CP_WAIT0()  asm volatile("cp.async.wait_group 0;" ::: "memory")

__device__ __forceinline__ void ldsm_x4(uint32_t& r0, uint32_t& r1, uint32_t& r2,
                                        uint32_t& r3, uint32_t addr) {
    asm volatile("ldmatrix.sync.aligned.m8n8.x4.shared.b16 {%0,%1,%2,%3}, [%4];"
                 : "=r"(r0), "=r"(r1), "=r"(r2), "=r"(r3) : "r"(addr));
}
__device__ __forceinline__ void mma_bf16(float* c, uint32_t a0, uint32_t a1,
                                         uint32_t a2, uint32_t a3,
                                         uint32_t b0, uint32_t b1) {
    asm volatile("mma.sync.aligned.m16n8k16.row.col.f32.bf16.bf16.f32 "
                 "{%0,%1,%2,%3},{%4,%5,%6,%7},{%8,%9},{%0,%1,%2,%3};"
                 : "+f"(c[0]), "+f"(c[1]), "+f"(c[2]), "+f"(c[3])
                 : "r"(a0), "r"(a1), "r"(a2), "r"(a3), "r"(b0), "r"(b1));
}

// SW128 swizzle on byte offsets (128B rows): conflict-free ldmatrix
#define SWZ(x) ((x) ^ (((x) >> 3) & 0x70))

// -------------------- small helpers --------------------
__device__ __forceinline__ unsigned int ordf(float f) {
    unsigned int u = __float_as_uint(f);
    return (u & 0x80000000u) ? ~u : (u | 0x80000000u);
}
__device__ __forceinline__ float unordf(unsigned int u) {
    return __uint_as_float((u & 0x80000000u) ? (u ^ 0x80000000u) : ~u);
}

__device__ __forceinline__ float blockSum256(float v) {
    __shared__ float sh[8];
    #pragma unroll
    for (int o = 16; o; o >>= 1) v += __shfl_down_sync(0xffffffffu, v, o);
    if ((threadIdx.x & 31) == 0) sh[threadIdx.x >> 5] = v;
    __syncthreads();
    float r = 0.f;
    if (threadIdx.x < 8) {
        r = sh[threadIdx.x];
        #pragma unroll
        for (int o = 4; o; o >>= 1) r += __shfl_down_sync(0xffu, r, o);
        if (threadIdx.x == 0) sh[0] = r;
    }
    __syncthreads();
    r = sh[0];
    __syncthreads();
    return r;
}
__device__ __forceinline__ float blockMax256(float v) {
    __shared__ float sh[8];
    #pragma unroll
    for (int o = 16; o; o >>= 1) v = fmaxf(v, __shfl_down_sync(0xffffffffu, v, o));
    if ((threadIdx.x & 31) == 0) sh[threadIdx.x >> 5] = v;
    __syncthreads();
    float r = -3.4e38f;
    if (threadIdx.x < 8) {
        r = sh[threadIdx.x];
        #pragma unroll
        for (int o = 4; o; o >>= 1) r = fmaxf(r, __shfl_down_sync(0xffu, r, o));
        if (threadIdx.x == 0) sh[0] = r;
    }
    __syncthreads();
    r = sh[0];
    __syncthreads();
    return r;
}

// -------------------- kernels --------------------
__global__ void init_kernel() {
    if (threadIdx.x < 256) d_hist[threadIdx.x] = 0u;
    if (threadIdx.x == 0) {
        d_prefix = 0u;
        d_need   = KSEL;
        d_eqctr  = 0;
        d_acc    = 0.0;
    }
}

// fp32 -> bf16 conversion for U rows and global_logit, fused with row-norm sums
__global__ void convert_kernel(const float* __restrict__ outputs,
                               const float* __restrict__ gl) {
    int row = blockIdx.x;              // [0, NUNL+KDIM)
    bool isA = (row < NUNL);
    const float* src = isA ? outputs + (size_t)(NPOS + row) * KDIM
                           : gl + (size_t)(row - NUNL) * KDIM;
    __nv_bfloat16* dst = isA ? d_Abf + (size_t)row * KDIM
                             : d_Bbf + (size_t)(row - NUNL) * KDIM;
    int t = threadIdx.x;               // 128 threads, 8 floats each
    float4 v0 = ((const float4*)src)[2 * t];
    float4 v1 = ((const float4*)src)[2 * t + 1];
    float s = v0.x * v0.x + v0.y * v0.y + v0.z * v0.z + v0.w * v0.w
            + v1.x * v1.x + v1.y * v1.y + v1.z * v1.z + v1.w * v1.w;
    __nv_bfloat162 h0 = __floats2bfloat162_rn(v0.x, v0.y);
    __nv_bfloat162 h1 = __floats2bfloat162_rn(v0.z, v0.w);
    __nv_bfloat162 h2 = __floats2bfloat162_rn(v1.x, v1.y);
    __nv_bfloat162 h3 = __floats2bfloat162_rn(v1.z, v1.w);
    uint4 pk;
    pk.x = *reinterpret_cast<unsigned int*>(&h0);
    pk.y = *reinterpret_cast<unsigned int*>(&h1);
    pk.z = *reinterpret_cast<unsigned int*>(&h2);
    pk.w = *reinterpret_cast<unsigned int*>(&h3);
    ((uint4*)dst)[t] = pk;

    __shared__ float sh[4];
    #pragma unroll
    for (int o = 16; o; o >>= 1) s += __shfl_down_sync(0xffffffffu, s, o);
    if ((t & 31) == 0) sh[t >> 5] = s;
    __syncthreads();
    if (t == 0) {
        float tot = sh[0] + sh[1] + sh[2] + sh[3];
        if (isA) d_u2[row] = tot;
        else     d_g2[row - NUNL] = tot;
    }
}

// bf16 HMMA GEMM (dot[u,c]) with fused min/argmin of (g2[c] - 2*dot) epilogue.
// 512 CTAs x 256 threads; warp grid 2(m) x 4(n); warp tile 64x32.
// 3-stage cp.async pipeline, ONE __syncthreads per iteration:
//   iter it: [wait -> sync -> compute(it) -> issue load(it+2)]
//   Race-free: sync(it) implies all warps finished compute(it-1); the load
//   target (it+2)%3 == (it-1)%3 is only touched post-sync, while the slowest
//   warp is at worst in compute(it) on buffer it%3.
__global__ void __launch_bounds__(256, 2) gemm_kernel() {
    extern __shared__ char smem[];
    uint32_t sb = smem_to_u32(smem);
    int tid = threadIdx.x;
    int wid = tid >> 5;
    int lane = tid & 31;
    int warp_m = wid >> 2;         // 0..1
    int warp_n = wid & 3;          // 0..3

    float* g2s = (float*)(smem + SM_G2);
    unsigned long long* smin = (unsigned long long*)(smem + SM_MIN);

    // init epilogue smem (ordered before first use by the iter-0 sync)
    ((float4*)g2s)[tid] = ((const float4*)d_g2)[tid];     // 256 * 16B = 4KB
    if (tid < BM) smin[tid] = 0xFFFFFFFFFFFFFFFFULL;

    const char* Abase = (const char*)d_Abf + (size_t)blockIdx.x * BM * (KDIM * 2);
    const char* Bbase = (const char*)d_Bbf;

    auto load_stage = [&](int it) {
        int nb = it >> 4, kt = it & 15;
        uint32_t abuf = sb + SM_A + (it % 3) * 16384;
        uint32_t bbuf = sb + SM_B + (it % 3) * 16384;
        const char* Ag = Abase + (size_t)kt * 128;
        const char* Bg = Bbase + (size_t)nb * BN * (KDIM * 2) + (size_t)kt * 128;
        #pragma unroll
        for (int q = 0; q < 4; q++) {
            int idx = q * 256 + tid;
            int r = idx >> 3, u = idx & 7;
            cp16(abuf + SWZ(r * 128 + u * 16), Ag + (size_t)r * 2048 + u * 16);
            cp16(bbuf + SWZ(r * 128 + u * 16), Bg + (size_t)r * 2048 + u * 16);
        }
        CP_COMMIT();
    };

    float acc[4][4][4];
    #pragma unroll
    for (int mt = 0; mt < 4; mt++)
        #pragma unroll
        for (int nt = 0; nt < 4; nt++)
            #pragma unroll
            for (int j = 0; j < 4; j++) acc[mt][nt][j] = 0.f;

    load_stage(0);
    load_stage(1);
    for (int it = 0; it < TOT_IT; it++) {
        // complete loads for stage it (outstanding groups: {it, it+1})
        if (it < TOT_IT - 1) CP_WAIT1(); else CP_WAIT0();
        __syncthreads();

        // compute on buffer it%3: 4 k16-steps
        uint32_t aoff = sb + SM_A + (it % 3) * 16384;
        uint32_t boff = sb + SM_B + (it % 3) * 16384;
        #pragma unroll
        for (int ks = 0; ks < 4; ks++) {
            uint32_t a[4][4];
            #pragma unroll
            for (int mt = 0; mt < 4; mt++) {
                int row = warp_m * 64 + mt * 16 + (lane & 15);
                uint32_t addr = aoff + SWZ(row * 128 + ks * 32 + ((lane >> 4) * 16));
                ldsm_x4(a[mt][0], a[mt][1], a[mt][2], a[mt][3], addr);
            }
            uint32_t b[4][2];
            #pragma unroll
            for (int h = 0; h < 2; h++) {
                int row = warp_n * 32 + h * 16 + ((lane >> 4) << 3) + (lane & 7);
                uint32_t addr = boff + SWZ(row * 128 + ks * 32 + (((lane >> 3) & 1) * 16));
                uint32_t r0, r1, r2, r3;
                ldsm_x4(r0, r1, r2, r3, addr);
                b[2 * h][0] = r0; b[2 * h][1] = r1;
                b[2 * h + 1][0] = r2; b[2 * h + 1][1] = r3;
            }
            #pragma unroll
            for (int mt = 0; mt < 4; mt++)
                #pragma unroll
                for (int nt = 0; nt < 4; nt++)
                    mma_bf16(acc[mt][nt], a[mt][0], a[mt][1], a[mt][2], a[mt][3],
                             b[nt][0], b[nt][1]);
        }

        // prefetch stage it+2 (writes buffer (it-1)%3, safe post-sync)
        if (it + 2 < TOT_IT) load_stage(it + 2);

        // end of an n-chunk: fold accumulators into the running min, reset
        if ((it & 15) == 15) {
            int nb = it >> 4;
            #pragma unroll
            for (int mt = 0; mt < 4; mt++) {
                unsigned long long bestA = 0xFFFFFFFFFFFFFFFFULL;
                unsigned long long bestB = 0xFFFFFFFFFFFFFFFFULL;
                #pragma unroll
                for (int nt = 0; nt < 4; nt++) {
                    int col = nb * BN + warp_n * 32 + nt * 8 + (lane & 3) * 2;
                    #pragma unroll
                    for (int j = 0; j < 2; j++) {
                        float s0 = g2s[col + j] - 2.0f * acc[mt][nt][j];
                        unsigned long long p =
                            ((unsigned long long)ordf(s0) << 32) | (unsigned)(col + j);
                        bestA = (p < bestA) ? p : bestA;
                        float s1 = g2s[col + j] - 2.0f * acc[mt][nt][2 + j];
                        p = ((unsigned long long)ordf(s1) << 32) | (unsigned)(col + j);
                        bestB = (p < bestB) ? p : bestB;
                        acc[mt][nt][j] = 0.f;
                        acc[mt][nt][2 + j] = 0.f;
                    }
                }
                // lanes 4k..4k+3 share the same output row: reduce in-warp first
                unsigned long long t;
                t = __shfl_down_sync(0xffffffffu, bestA, 2); bestA = (t < bestA) ? t : bestA;
                t = __shfl_down_sync(0xffffffffu, bestA, 1); bestA = (t < bestA) ? t : bestA;
                t = __shfl_down_sync(0xffffffffu, bestB, 2); bestB = (t < bestB) ? t : bestB;
                t = __shfl_down_sync(0xffffffffu, bestB, 1); bestB = (t < bestB) ? t : bestB;
                if ((lane & 3) == 0) {
                    int row0 = warp_m * 64 + mt * 16 + (lane >> 2);
                    atomicMin(&smin[row0], bestA);
                    atomicMin(&smin[row0 + 8], bestB);
                }
            }
        }
    }

    __syncthreads();
    if (tid < BM) d_minpack[blockIdx.x * BM + tid] = smin[tid];
}

// key = max(u2 + s_min, 0); pseudo-label = argmin
__global__ void keys2_kernel() {
    int u = blockIdx.x * 256 + threadIdx.x;
    unsigned long long pk = d_minpack[u];
    float smin = unordf((unsigned int)(pk >> 32));
    float key = d_u2[u] + smin;
    if (key < 0.f) key = 0.f;
    d_keys[u]   = ordf(key);
    d_plabel[u] = (int)(pk & 0xFFFFFFFFu);
}

// 4-pass radix select for the KSEL-th smallest key
__global__ void hist_kernel(int shift) {
    __shared__ unsigned int sh[256];
    sh[threadIdx.x] = 0u;
    __syncthreads();
    unsigned int prefix = d_prefix;
    unsigned int known  = (shift == 24) ? 0u : (0xFFFFFFFFu << (shift + 8));
    for (int i = blockIdx.x * blockDim.x + threadIdx.x; i < NUNL;
         i += gridDim.x * blockDim.x) {
        unsigned int k = d_keys[i];
        if ((k & known) == (prefix & known))
            atomicAdd(&sh[(k >> shift) & 0xFFu], 1u);
    }
    __syncthreads();
    if (sh[threadIdx.x]) atomicAdd(&d_hist[threadIdx.x], sh[threadIdx.x]);
}

__global__ void scan_kernel(int shift) {
    __shared__ unsigned int sh[256];
    sh[threadIdx.x] = d_hist[threadIdx.x];
    __syncthreads();
    if (threadIdx.x == 0) {
        int need = d_need;
        unsigned int cum = 0;
        int b = 255;
        for (int i = 0; i < 256; i++) {
            unsigned int c2 = cum + sh[i];
            if ((int)c2 >= need) { b = i; break; }
            cum = c2;
        }
        d_prefix |= ((unsigned int)b << shift);
        d_need = need - (int)cum;
        if (shift == 0) {
            d_T = d_prefix;
            d_selEq = d_need;
            d_eqctr = 0;
        }
    }
    __syncthreads();
    d_hist[threadIdx.x] = 0u;
}

__global__ void select_kernel() {
    int u = blockIdx.x * blockDim.x + threadIdx.x;
    if (u >= NUNL) return;
    unsigned int k = d_keys[u];
    unsigned int T = d_T;
    int lbl = -1;
    if (k < T) lbl = d_plabel[u];
    else if (k == T) {
        if (atomicAdd(&d_eqctr, 1) < d_selEq) lbl = d_plabel[u];
    }
    d_sel_label[NPOS + u] = lbl;
}

// cross entropy over P rows + selected U rows, double accumulator
__global__ void ce_kernel(const float* __restrict__ outputs,
                          const int* __restrict__ labels) {
    int r = blockIdx.x;
    int lab = labels[r];
    int target = (lab < KDIM) ? lab : d_sel_label[r];
    if (target < 0) return;
    const float4* p = (const float4*)(outputs + (size_t)r * KDIM);
    float4 v = p[threadIdx.x];
    float m = fmaxf(fmaxf(v.x, v.y), fmaxf(v.z, v.w));
    float M = blockMax256(m);
    float e = expf(v.x - M) + expf(v.y - M) + expf(v.z - M) + expf(v.w - M);
    float S = blockSum256(e);
    if (threadIdx.x == 0) {
        float xt = outputs[(size_t)r * KDIM + target];
        float nll = logf(S) + M - xt;
        atomicAdd(&d_acc, (double)nll);
    }
}

__global__ void finish_kernel(float* out) {
    out[0] = (float)(d_acc / (double)NCOMB);
}

// -------------------- launch --------------------
extern "C" void kernel_launch(void* const* d_in, const int* in_sizes, int n_in,
                              void* d_out, int out_size) {
    const float* outputs = (const float*)d_in[0];
    const int*   labels  = (const int*)d_in[1];
    const float* gl      = (const float*)d_in[2];
    float* out = (float*)d_out;

    cudaFuncSetAttribute(gemm_kernel, cudaFuncAttributeMaxDynamicSharedMemorySize,
                         SMEM_TOTAL);

    init_kernel<<<1, 256>>>();
    convert_kernel<<<NUNL + KDIM, 128>>>(outputs, gl);
    gemm_kernel<<<GRID_M, 256, SMEM_TOTAL>>>();
    keys2_kernel<<<NUNL / 256, 256>>>();
    for (int pass = 0; pass < 4; pass++) {
        int shift = 24 - 8 * pass;
        hist_kernel<<<64, 256>>>(shift);
        scan_kernel<<<1, 256>>>(shift);
    }
    select_kernel<<<NUNL / 256, 256>>>();
    ce_kernel<<<BTOT, 256>>>(outputs, labels);
    finish_kernel<<<1, 1>>>(out);
}